// round 1
// baseline (speedup 1.0000x reference)
#include <cuda_runtime.h>
#include <math.h>

// ---------------- problem constants ----------------
#define BATCH 4
#define SEQ 1024
#define DM 512          // d_model
#define LAT 1024        // latent = 32*32
#define DIN 1024        // d_inner
#define DSTATE 16
#define DTRANK 32
#define NL 4
#define ROWS (BATCH*SEQ)   // 4096

// ---------------- scratch (static device memory; no allocs) ----------------
__device__ float g_h[ROWS*DM];
__device__ float g_hn[ROWS*DM];
__device__ float g_xz[ROWS*2*DIN];      // [xp | z], row stride 2048
__device__ float g_xc[ROWS*DIN];        // conv+silu output (u)
__device__ float g_dbl[ROWS*64];        // [dt_in(32) | B(16) | C(16)]
__device__ float g_dt[ROWS*DIN];
__device__ float g_ym[ROWS*DIN];        // gated scan output
__device__ float g_logits[ROWS*LAT];

// ---------------- helpers ----------------
__device__ __forceinline__ float softplusf(float x) {
    return x > 20.f ? x : log1pf(__expf(x));
}
__device__ __forceinline__ float siluf(float x) {
    return x / (1.f + __expf(-x));
}

// ---------------- generic register-blocked SGEMM ----------------
// C[M,N] = act(A[M,K](lda) @ B[K,N] + bias) + resid
// ACT: 0=none, 1=softplus.  All dims assumed divisible by tiles (true here).
template<int BM, int BN, int BK, int TM, int TN, int ACT, bool BIAS, bool RESID>
__global__ void sgemm_kernel(const float* __restrict__ A, int lda,
                             const float* __restrict__ B,
                             const float* __restrict__ bias,
                             const float* __restrict__ resid,
                             float* __restrict__ C,
                             int M, int N, int K)
{
    __shared__ float As[BK][BM];
    __shared__ float Bs[BK][BN + 4];

    const int tid = threadIdx.x;               // (BM/TM)*(BN/TN) threads
    const int bm0 = blockIdx.y * BM;
    const int bn0 = blockIdx.x * BN;

    const int a_row = tid / (BK / 4);
    const int a_col = (tid % (BK / 4)) * 4;
    const int b_row = tid / (BN / 4);
    const int b_col = (tid % (BN / 4)) * 4;

    const int tx = tid % (BN / TN);
    const int ty = tid / (BN / TN);

    float acc[TM][TN];
#pragma unroll
    for (int i = 0; i < TM; i++)
#pragma unroll
        for (int j = 0; j < TN; j++) acc[i][j] = 0.f;

    const float* Ap = A + (size_t)(bm0 + a_row) * lda + a_col;
    const float* Bp = B + (size_t)b_row * N + bn0 + b_col;

    for (int k0 = 0; k0 < K; k0 += BK) {
        float4 av = *reinterpret_cast<const float4*>(Ap + k0);
        float4 bv = *reinterpret_cast<const float4*>(Bp + (size_t)k0 * N);
        As[a_col + 0][a_row] = av.x;
        As[a_col + 1][a_row] = av.y;
        As[a_col + 2][a_row] = av.z;
        As[a_col + 3][a_row] = av.w;
        *reinterpret_cast<float4*>(&Bs[b_row][b_col]) = bv;
        __syncthreads();
#pragma unroll
        for (int kk = 0; kk < BK; kk++) {
            float a[TM], b[TN];
#pragma unroll
            for (int i = 0; i < TM; i++) a[i] = As[kk][ty * TM + i];
#pragma unroll
            for (int j = 0; j < TN; j++) b[j] = Bs[kk][tx * TN + j];
#pragma unroll
            for (int i = 0; i < TM; i++)
#pragma unroll
                for (int j = 0; j < TN; j++)
                    acc[i][j] = fmaf(a[i], b[j], acc[i][j]);
        }
        __syncthreads();
    }

#pragma unroll
    for (int i = 0; i < TM; i++) {
        const int row = bm0 + ty * TM + i;
#pragma unroll
        for (int j = 0; j < TN; j++) {
            const int col = bn0 + tx * TN + j;
            float v = acc[i][j];
            if (BIAS)  v += bias[col];
            if (ACT == 1) v = softplusf(v);
            if (RESID) v += resid[(size_t)row * N + col];
            C[(size_t)row * N + col] = v;
        }
    }
}

// ---------------- rmsnorm (one block per row of 512) ----------------
__global__ void rmsnorm_kernel(const float* __restrict__ x,
                               const float* __restrict__ w,
                               float* __restrict__ o)
{
    const int row = blockIdx.x;
    const int t = threadIdx.x;                  // 128 threads, float4 each
    const float4 v = reinterpret_cast<const float4*>(x + (size_t)row * DM)[t];
    float ss = v.x * v.x + v.y * v.y + v.z * v.z + v.w * v.w;
#pragma unroll
    for (int off = 16; off; off >>= 1) ss += __shfl_xor_sync(~0u, ss, off);
    __shared__ float sm[4];
    if ((t & 31) == 0) sm[t >> 5] = ss;
    __syncthreads();
    const float tot = sm[0] + sm[1] + sm[2] + sm[3];
    const float sc = rsqrtf(tot / (float)DM + 1e-5f);
    const float4 wv = reinterpret_cast<const float4*>(w)[t];
    float4 r;
    r.x = v.x * sc * wv.x; r.y = v.y * sc * wv.y;
    r.z = v.z * sc * wv.z; r.w = v.w * sc * wv.w;
    reinterpret_cast<float4*>(o + (size_t)row * DM)[t] = r;
}

// ---------------- causal depthwise conv (K=4) + silu ----------------
// reads xp = xz[:, :DIN] (row stride 2*DIN), writes xc (row stride DIN)
__global__ void conv_silu_kernel(const float* __restrict__ xz,
                                 const float* __restrict__ w,
                                 const float* __restrict__ b,
                                 float* __restrict__ out)
{
    const int idx = blockIdx.x * blockDim.x + threadIdx.x;  // ROWS*DIN
    const int d = idx & (DIN - 1);
    const int bt = idx >> 10;
    const int t = bt & (SEQ - 1);
    const float* col = xz + (size_t)bt * (2 * DIN) + d;
    const float w0 = w[d * 4 + 0], w1 = w[d * 4 + 1];
    const float w2 = w[d * 4 + 2], w3 = w[d * 4 + 3];
    float acc = b[d] + w3 * col[0];
    if (t >= 1) acc = fmaf(w2, col[-1 * 2 * DIN], acc);
    if (t >= 2) acc = fmaf(w1, col[-2 * 2 * DIN], acc);
    if (t >= 3) acc = fmaf(w0, col[-3 * 2 * DIN], acc);
    out[idx] = siluf(acc);
}

// ---------------- selective scan ----------------
// warp = 2 channels x 16 states. h_n recurrence per lane; y via shfl reduce.
// Writes ym = (y + u*D) * silu(z) directly.
__global__ void scan_kernel(const float* __restrict__ u,
                            const float* __restrict__ dt,
                            const float* __restrict__ dbl,
                            const float* __restrict__ A_log,
                            const float* __restrict__ Dp,
                            const float* __restrict__ z,   // row stride 2*DIN
                            float* __restrict__ ym)
{
    const int warp = (blockIdx.x * blockDim.x + threadIdx.x) >> 5;
    const int lane = threadIdx.x & 31;
    const int n = lane & 15;
    const int ch = warp * 2 + (lane >> 4);     // pairs never cross batches
    const int b = ch >> 10;
    const int d = ch & (DIN - 1);

    const float An = -__expf(A_log[d * DSTATE + n]);
    const float Dd = Dp[d];
    float h = 0.f;

    const float* dtp = dt + (size_t)b * SEQ * DIN + d;
    const float* up  = u  + (size_t)b * SEQ * DIN + d;
    const float* blp = dbl + (size_t)b * SEQ * 64 + DTRANK + n;  // B at +32, C at +48
    const float* zp  = z  + (size_t)b * SEQ * 2 * DIN + d;
    float* yp        = ym + (size_t)b * SEQ * DIN + d;

    float dt_v = dtp[0], u_v = up[0], Bv = blp[0], Cv = blp[DSTATE];

    for (int t = 0; t < SEQ; t++) {
        float dtn = 0.f, un = 0.f, Bn = 0.f, Cn = 0.f;
        if (t + 1 < SEQ) {                      // prefetch next step
            dtn = dtp[(t + 1) * DIN];
            un  = up[(t + 1) * DIN];
            Bn  = blp[(t + 1) * 64];
            Cn  = blp[(t + 1) * 64 + DSTATE];
        }
        const float dA = __expf(dt_v * An);
        h = fmaf(dA, h, dt_v * u_v * Bv);
        float p = h * Cv;
        p += __shfl_xor_sync(~0u, p, 8);
        p += __shfl_xor_sync(~0u, p, 4);
        p += __shfl_xor_sync(~0u, p, 2);
        p += __shfl_xor_sync(~0u, p, 1);
        if (n == 0) {
            const float y = p + u_v * Dd;
            const float zv = zp[(size_t)t * 2 * DIN];
            yp[(size_t)t * DIN] = y * siluf(zv);
        }
        dt_v = dtn; u_v = un; Bv = Bn; Cv = Cn;
    }
}

// ---------------- grouped softmax (32 groups of 32 per row) ----------------
__global__ void softmax_kernel(const float* __restrict__ logits,
                               float* __restrict__ out)
{
    const int g = (blockIdx.x * blockDim.x + threadIdx.x) >> 5;  // ROWS*32 groups
    const int lane = threadIdx.x & 31;
    const size_t base = (size_t)(g >> 5) * LAT + (size_t)(g & 31) * 32;
    const float v = logits[base + lane];
    float m = v;
#pragma unroll
    for (int off = 16; off; off >>= 1) m = fmaxf(m, __shfl_xor_sync(~0u, m, off));
    const float e = __expf(v - m);
    float s = e;
#pragma unroll
    for (int off = 16; off; off >>= 1) s += __shfl_xor_sync(~0u, s, off);
    out[base + lane] = e / s;
}

// ---------------- host-side launch sequence ----------------
static inline float* symaddr(const void* sym) {
    void* p = nullptr;
    cudaGetSymbolAddress(&p, sym);
    return (float*)p;
}

extern "C" void kernel_launch(void* const* d_in, const int* in_sizes, int n_in,
                              void* d_out, int out_size)
{
    const float* x       = (const float*)d_in[0];
    const float* lin1_w  = (const float*)d_in[1];
    const float* lin1_b  = (const float*)d_in[2];
    const float* norm_w  = (const float*)d_in[3];
    const float* in_w    = (const float*)d_in[4];
    const float* conv_w  = (const float*)d_in[5];
    const float* conv_b  = (const float*)d_in[6];
    const float* xproj_w = (const float*)d_in[7];
    const float* dt_w    = (const float*)d_in[8];
    const float* dt_b    = (const float*)d_in[9];
    const float* A_log   = (const float*)d_in[10];
    const float* Dp      = (const float*)d_in[11];
    const float* out_w   = (const float*)d_in[12];
    const float* lin2_w  = (const float*)d_in[13];
    const float* lin2_b  = (const float*)d_in[14];
    float* outp          = (float*)d_out;

    float* p_h      = symaddr(g_h);
    float* p_hn     = symaddr(g_hn);
    float* p_xz     = symaddr(g_xz);
    float* p_xc     = symaddr(g_xc);
    float* p_dbl    = symaddr(g_dbl);
    float* p_dt     = symaddr(g_dt);
    float* p_ym     = symaddr(g_ym);
    float* p_logits = symaddr(g_logits);

    // 1) h = x @ lin1_w + lin1_b   (4096x1024 @ 1024x512)
    sgemm_kernel<128,128,8,8,8,0,true,false><<<dim3(DM/128, ROWS/128), 256>>>(
        x, LAT, lin1_w, lin1_b, nullptr, p_h, ROWS, DM, LAT);

    for (int l = 0; l < NL; l++) {
        // 2a) rmsnorm
        rmsnorm_kernel<<<ROWS, DM/4>>>(p_h, norm_w + (size_t)l * DM, p_hn);

        // 2b) xz = hn @ in_w[l]   (4096x512 @ 512x2048)
        sgemm_kernel<128,128,8,8,8,0,false,false><<<dim3(2*DIN/128, ROWS/128), 256>>>(
            p_hn, DM, in_w + (size_t)l * DM * 2 * DIN, nullptr, nullptr,
            p_xz, ROWS, 2*DIN, DM);

        // 2c) xp = silu(causal_dwconv(xz[:, :DIN]))
        conv_silu_kernel<<<(ROWS*DIN)/256, 256>>>(
            p_xz, conv_w + (size_t)l * DIN * 4, conv_b + (size_t)l * DIN, p_xc);

        // 2d) dbl = xc @ xproj_w[l]   (4096x1024 @ 1024x64)
        sgemm_kernel<64,64,16,4,4,0,false,false><<<dim3(64/64, ROWS/64), 256>>>(
            p_xc, DIN, xproj_w + (size_t)l * DIN * 64, nullptr, nullptr,
            p_dbl, ROWS, 64, DIN);

        // 2e) dt = softplus(dbl[:, :32] @ dt_w[l] + dt_b[l])  (4096x32 @ 32x1024)
        sgemm_kernel<128,128,8,8,8,1,true,false><<<dim3(DIN/128, ROWS/128), 256>>>(
            p_dbl, 64, dt_w + (size_t)l * DTRANK * DIN, dt_b + (size_t)l * DIN,
            nullptr, p_dt, ROWS, DIN, DTRANK);

        // 2f) selective scan + D-skip + silu(z) gate  ->  ym
        scan_kernel<<<(BATCH*DIN/2)*32/256, 256>>>(
            p_xc, p_dt, p_dbl,
            A_log + (size_t)l * DIN * DSTATE, Dp + (size_t)l * DIN,
            p_xz + DIN, p_ym);

        // 2g) h = h + ym @ out_w[l]   (4096x1024 @ 1024x512)
        sgemm_kernel<128,128,8,8,8,0,false,true><<<dim3(DM/128, ROWS/128), 256>>>(
            p_ym, DIN, out_w + (size_t)l * DIN * DM, nullptr, p_h,
            p_h, ROWS, DM, DIN);
    }

    // 3) logits = h @ lin2_w + lin2_b   (4096x512 @ 512x1024)
    sgemm_kernel<128,128,8,8,8,0,true,false><<<dim3(LAT/128, ROWS/128), 256>>>(
        p_h, DM, lin2_w, lin2_b, nullptr, p_logits, ROWS, LAT, DM);

    // 4) grouped softmax -> out
    softmax_kernel<<<(ROWS*32*32)/256, 256>>>(p_logits, outp);
}

// round 3
// speedup vs baseline: 1.3849x; 1.3849x over previous
#include <cuda_runtime.h>
#include <math.h>
#include <stdint.h>

// ---------------- problem constants ----------------
#define BATCH 4
#define SEQ 1024
#define DM 512          // d_model
#define LAT 1024        // latent
#define DIN 1024        // d_inner
#define DSTATE 16
#define DTRANK 32
#define NL 4
#define ROWS (BATCH*SEQ)   // 4096

// ---------------- scratch ----------------
__device__ float g_h[ROWS*DM];
__device__ float g_hn[ROWS*DM];
__device__ float g_xz[ROWS*2*DIN];
__device__ float g_xc[ROWS*DIN];
__device__ float g_dbl[ROWS*64];
__device__ float g_dt[ROWS*DIN];
__device__ float g_ym[ROWS*DIN];
__device__ float g_logits[ROWS*LAT];

// ---------------- helpers ----------------
__device__ __forceinline__ float softplusf(float x) {
    return x > 20.f ? x : log1pf(__expf(x));
}
__device__ __forceinline__ float siluf(float x) {
    return x / (1.f + __expf(-x));
}
__device__ __forceinline__ uint32_t smem_u32(const void* p) {
    uint32_t a;
    asm("{ .reg .u64 t; cvta.to.shared.u64 t, %1; cvt.u32.u64 %0, t; }" : "=r"(a) : "l"(p));
    return a;
}
__device__ __forceinline__ uint32_t cvt_tf32(float f) {
    uint32_t r;
    asm("cvt.rna.tf32.f32 %0, %1;" : "=r"(r) : "f"(f));
    return r;
}
__device__ __forceinline__ void mma_16n8k8(float* d, const uint32_t* a, const uint32_t* b) {
    asm volatile(
        "mma.sync.aligned.m16n8k8.row.col.f32.tf32.tf32.f32 "
        "{%0,%1,%2,%3}, {%4,%5,%6,%7}, {%8,%9}, {%0,%1,%2,%3};"
        : "+f"(d[0]), "+f"(d[1]), "+f"(d[2]), "+f"(d[3])
        : "r"(a[0]), "r"(a[1]), "r"(a[2]), "r"(a[3]), "r"(b[0]), "r"(b[1]));
}

// ---------------- tf32 mma.sync GEMM ----------------
// C[M,N] = act(A[M,K](lda) @ B[K,N] + bias) + resid
// BM=128, BK=32, BN in {64,128}. 256 threads = 8 warps (2x4), warp tile 64x(BN/4).
template<int BN, int ACT, bool BIAS, bool RESID>
__global__ __launch_bounds__(256) void gemm_mma(
    const float* __restrict__ A, int lda,
    const float* __restrict__ B,
    const float* __restrict__ bias,
    const float* __restrict__ resid,
    float* __restrict__ C, int N, int K)
{
    constexpr int BM = 128, BK = 32;
    constexpr int ASTR = BM + 4;       // 132
    constexpr int BSTR = BN + 4;
    constexpr int NI = BN / 32;        // n-tiles (m16n8) per warp: 4 or 2
    constexpr int CPI = BN / 32;       // cp.async float4 iters (BK*BN/4/256)

    extern __shared__ uint32_t smraw[];
    uint32_t* AsBuf[2] = { smraw, smraw + BK * ASTR };
    float* Bbase = (float*)(smraw + 2 * BK * ASTR);
    float* BsBuf[2] = { Bbase, Bbase + BK * BSTR };

    const int tid = threadIdx.x;
    const int wid = tid >> 5, lane = tid & 31;
    const int g = lane >> 2, tig = lane & 3;
    const int warpM = wid >> 2, warpN = wid & 3;
    const int bm0 = blockIdx.y * BM, bn0 = blockIdx.x * BN;
    const int KT = K / BK;

    float acc[4][NI][4];
#pragma unroll
    for (int mi = 0; mi < 4; mi++)
#pragma unroll
        for (int ni = 0; ni < NI; ni++)
#pragma unroll
            for (int j = 0; j < 4; j++) acc[mi][ni][j] = 0.f;

    float4 areg[4];

    auto ldgA = [&](int kt) {
#pragma unroll
        for (int i = 0; i < 4; i++) {
            int v = tid + i * 256;
            int r = v >> 3, c4 = v & 7;
            areg[i] = *(const float4*)(A + (size_t)(bm0 + r) * lda + kt * 32 + c4 * 4);
        }
    };
    auto stsA = [&](int s) {
#pragma unroll
        for (int i = 0; i < 4; i++) {
            int v = tid + i * 256;
            int r = v >> 3, c4 = v & 7;
            uint32_t* dst = AsBuf[s] + (c4 * 4) * ASTR + r;
            dst[0 * ASTR] = cvt_tf32(areg[i].x);
            dst[1 * ASTR] = cvt_tf32(areg[i].y);
            dst[2 * ASTR] = cvt_tf32(areg[i].z);
            dst[3 * ASTR] = cvt_tf32(areg[i].w);
        }
    };
    auto cpB = [&](int kt, int s) {
#pragma unroll
        for (int i = 0; i < CPI; i++) {
            int v = tid + i * 256;
            int kr = v / (BN / 4), n4 = v % (BN / 4);
            uint32_t dst = smem_u32(BsBuf[s] + kr * BSTR + n4 * 4);
            const float* src = B + (size_t)(kt * 32 + kr) * N + bn0 + n4 * 4;
            asm volatile("cp.async.cg.shared.global [%0], [%1], 16;" :: "r"(dst), "l"(src));
        }
        asm volatile("cp.async.commit_group;" ::: "memory");
    };
    auto compute = [&](int s) {
        const uint32_t* as = AsBuf[s];
        const float* bs = BsBuf[s];
#pragma unroll
        for (int k8 = 0; k8 < BK; k8 += 8) {
            uint32_t af[4][4];
            uint32_t bf[NI][2];
#pragma unroll
            for (int mi = 0; mi < 4; mi++) {
                int m0 = warpM * 64 + mi * 16 + g;
                const uint32_t* p = as + (k8 + tig) * ASTR + m0;
                const uint32_t* q = as + (k8 + tig + 4) * ASTR + m0;
                af[mi][0] = p[0]; af[mi][1] = p[8];
                af[mi][2] = q[0]; af[mi][3] = q[8];
            }
#pragma unroll
            for (int ni = 0; ni < NI; ni++) {
                int n0 = warpN * (BN / 4) + ni * 8 + g;
                bf[ni][0] = cvt_tf32(bs[(k8 + tig) * BSTR + n0]);
                bf[ni][1] = cvt_tf32(bs[(k8 + tig + 4) * BSTR + n0]);
            }
#pragma unroll
            for (int mi = 0; mi < 4; mi++)
#pragma unroll
                for (int ni = 0; ni < NI; ni++)
                    mma_16n8k8(acc[mi][ni], af[mi], bf[ni]);
        }
    };

    // prologue
    ldgA(0);
    cpB(0, 0);
    stsA(0);
    asm volatile("cp.async.wait_group 0;" ::: "memory");
    __syncthreads();

    for (int kt = 0; kt < KT; kt++) {
        const int s = kt & 1;
        const bool pref = (kt + 1 < KT);
        if (pref) { ldgA(kt + 1); cpB(kt + 1, s ^ 1); }
        compute(s);
        if (pref) {
            stsA(s ^ 1);
            asm volatile("cp.async.wait_group 0;" ::: "memory");
        }
        __syncthreads();
    }

    // epilogue: registers -> gmem (float2 per fragment row), fused bias/act/resid
#pragma unroll
    for (int mi = 0; mi < 4; mi++) {
        const int r0 = bm0 + warpM * 64 + mi * 16 + g;
#pragma unroll
        for (int ni = 0; ni < NI; ni++) {
            const int c = bn0 + warpN * (BN / 4) + ni * 8 + tig * 2;
            float2 v0 = make_float2(acc[mi][ni][0], acc[mi][ni][1]);
            float2 v1 = make_float2(acc[mi][ni][2], acc[mi][ni][3]);
            if (BIAS) {
                const float b0 = bias[c], b1 = bias[c + 1];
                v0.x += b0; v0.y += b1; v1.x += b0; v1.y += b1;
            }
            if (ACT == 1) {
                v0.x = softplusf(v0.x); v0.y = softplusf(v0.y);
                v1.x = softplusf(v1.x); v1.y = softplusf(v1.y);
            }
            if (RESID) {
                const float2 r0v = *(const float2*)(resid + (size_t)r0 * N + c);
                const float2 r1v = *(const float2*)(resid + (size_t)(r0 + 8) * N + c);
                v0.x += r0v.x; v0.y += r0v.y; v1.x += r1v.x; v1.y += r1v.y;
            }
            *(float2*)(C + (size_t)r0 * N + c) = v0;
            *(float2*)(C + (size_t)(r0 + 8) * N + c) = v1;
        }
    }
}

// ---------------- rmsnorm ----------------
__global__ void rmsnorm_kernel(const float* __restrict__ x,
                               const float* __restrict__ w,
                               float* __restrict__ o)
{
    const int row = blockIdx.x;
    const int t = threadIdx.x;
    const float4 v = reinterpret_cast<const float4*>(x + (size_t)row * DM)[t];
    float ss = v.x * v.x + v.y * v.y + v.z * v.z + v.w * v.w;
#pragma unroll
    for (int off = 16; off; off >>= 1) ss += __shfl_xor_sync(~0u, ss, off);
    __shared__ float sm[4];
    if ((t & 31) == 0) sm[t >> 5] = ss;
    __syncthreads();
    const float tot = sm[0] + sm[1] + sm[2] + sm[3];
    const float sc = rsqrtf(tot / (float)DM + 1e-5f);
    const float4 wv = reinterpret_cast<const float4*>(w)[t];
    float4 r;
    r.x = v.x * sc * wv.x; r.y = v.y * sc * wv.y;
    r.z = v.z * sc * wv.z; r.w = v.w * sc * wv.w;
    reinterpret_cast<float4*>(o + (size_t)row * DM)[t] = r;
}

// ---------------- causal depthwise conv (K=4) + silu ----------------
__global__ void conv_silu_kernel(const float* __restrict__ xz,
                                 const float* __restrict__ w,
                                 const float* __restrict__ b,
                                 float* __restrict__ out)
{
    const int idx = blockIdx.x * blockDim.x + threadIdx.x;
    const int d = idx & (DIN - 1);
    const int bt = idx >> 10;
    const int t = bt & (SEQ - 1);
    const float* col = xz + (size_t)bt * (2 * DIN) + d;
    const float w0 = w[d * 4 + 0], w1 = w[d * 4 + 1];
    const float w2 = w[d * 4 + 2], w3 = w[d * 4 + 3];
    float acc = b[d] + w3 * col[0];
    if (t >= 1) acc = fmaf(w2, col[-1 * 2 * DIN], acc);
    if (t >= 2) acc = fmaf(w1, col[-2 * 2 * DIN], acc);
    if (t >= 3) acc = fmaf(w0, col[-3 * 2 * DIN], acc);
    out[idx] = siluf(acc);
}

// ---------------- selective scan ----------------
__global__ void scan_kernel(const float* __restrict__ u,
                            const float* __restrict__ dt,
                            const float* __restrict__ dbl,
                            const float* __restrict__ A_log,
                            const float* __restrict__ Dp,
                            const float* __restrict__ z,
                            float* __restrict__ ym)
{
    const int warp = (blockIdx.x * blockDim.x + threadIdx.x) >> 5;
    const int lane = threadIdx.x & 31;
    const int n = lane & 15;
    const int ch = warp * 2 + (lane >> 4);
    const int b = ch >> 10;
    const int d = ch & (DIN - 1);

    const float An = -__expf(A_log[d * DSTATE + n]);
    const float Dd = Dp[d];
    float h = 0.f;

    const float* dtp = dt + (size_t)b * SEQ * DIN + d;
    const float* up  = u  + (size_t)b * SEQ * DIN + d;
    const float* blp = dbl + (size_t)b * SEQ * 64 + DTRANK + n;
    const float* zp  = z  + (size_t)b * SEQ * 2 * DIN + d;
    float* yp        = ym + (size_t)b * SEQ * DIN + d;

    float dt_v = dtp[0], u_v = up[0], Bv = blp[0], Cv = blp[DSTATE];

    for (int t = 0; t < SEQ; t++) {
        float dtn = 0.f, un = 0.f, Bn = 0.f, Cn = 0.f;
        if (t + 1 < SEQ) {
            dtn = dtp[(t + 1) * DIN];
            un  = up[(t + 1) * DIN];
            Bn  = blp[(t + 1) * 64];
            Cn  = blp[(t + 1) * 64 + DSTATE];
        }
        const float dA = __expf(dt_v * An);
        h = fmaf(dA, h, dt_v * u_v * Bv);
        float p = h * Cv;
        p += __shfl_xor_sync(~0u, p, 8);
        p += __shfl_xor_sync(~0u, p, 4);
        p += __shfl_xor_sync(~0u, p, 2);
        p += __shfl_xor_sync(~0u, p, 1);
        if (n == 0) {
            const float y = p + u_v * Dd;
            const float zv = zp[(size_t)t * 2 * DIN];
            yp[(size_t)t * DIN] = y * siluf(zv);
        }
        dt_v = dtn; u_v = un; Bv = Bn; Cv = Cn;
    }
}

// ---------------- grouped softmax ----------------
__global__ void softmax_kernel(const float* __restrict__ logits,
                               float* __restrict__ out)
{
    const int g = (blockIdx.x * blockDim.x + threadIdx.x) >> 5;
    const int lane = threadIdx.x & 31;
    const size_t base = (size_t)(g >> 5) * LAT + (size_t)(g & 31) * 32;
    const float v = logits[base + lane];
    float m = v;
#pragma unroll
    for (int off = 16; off; off >>= 1) m = fmaxf(m, __shfl_xor_sync(~0u, m, off));
    const float e = __expf(v - m);
    float s = e;
#pragma unroll
    for (int off = 16; off; off >>= 1) s += __shfl_xor_sync(~0u, s, off);
    out[base + lane] = e / s;
}

// ---------------- host side ----------------
static inline float* symaddr(const void* sym) {
    void* p = nullptr;
    cudaGetSymbolAddress(&p, sym);
    return (float*)p;
}

// smem: 2 * 32*132 uint (A) + 2 * 32*(BN+4) float (B)
#define SMEM_BN128 ((2*32*132 + 2*32*132) * 4)   // 67584
#define SMEM_BN64  ((2*32*132 + 2*32*68) * 4)    // 51200

extern "C" void kernel_launch(void* const* d_in, const int* in_sizes, int n_in,
                              void* d_out, int out_size)
{
    const float* x       = (const float*)d_in[0];
    const float* lin1_w  = (const float*)d_in[1];
    const float* lin1_b  = (const float*)d_in[2];
    const float* norm_w  = (const float*)d_in[3];
    const float* in_w    = (const float*)d_in[4];
    const float* conv_w  = (const float*)d_in[5];
    const float* conv_b  = (const float*)d_in[6];
    const float* xproj_w = (const float*)d_in[7];
    const float* dt_w    = (const float*)d_in[8];
    const float* dt_b    = (const float*)d_in[9];
    const float* A_log   = (const float*)d_in[10];
    const float* Dp      = (const float*)d_in[11];
    const float* out_w   = (const float*)d_in[12];
    const float* lin2_w  = (const float*)d_in[13];
    const float* lin2_b  = (const float*)d_in[14];
    float* outp          = (float*)d_out;

    float* p_h      = symaddr(g_h);
    float* p_hn     = symaddr(g_hn);
    float* p_xz     = symaddr(g_xz);
    float* p_xc     = symaddr(g_xc);
    float* p_dbl    = symaddr(g_dbl);
    float* p_dt     = symaddr(g_dt);
    float* p_ym     = symaddr(g_ym);
    float* p_logits = symaddr(g_logits);

    cudaFuncSetAttribute(gemm_mma<128,0,true,false>,  cudaFuncAttributeMaxDynamicSharedMemorySize, SMEM_BN128);
    cudaFuncSetAttribute(gemm_mma<128,0,false,false>, cudaFuncAttributeMaxDynamicSharedMemorySize, SMEM_BN128);
    cudaFuncSetAttribute(gemm_mma<128,1,true,false>,  cudaFuncAttributeMaxDynamicSharedMemorySize, SMEM_BN128);
    cudaFuncSetAttribute(gemm_mma<128,0,false,true>,  cudaFuncAttributeMaxDynamicSharedMemorySize, SMEM_BN128);
    cudaFuncSetAttribute(gemm_mma<64,0,false,false>,  cudaFuncAttributeMaxDynamicSharedMemorySize, SMEM_BN64);

    // 1) h = x @ lin1_w + lin1_b   (4096x1024x512)
    gemm_mma<128,0,true,false><<<dim3(DM/128, ROWS/128), 256, SMEM_BN128>>>(
        x, LAT, lin1_w, lin1_b, nullptr, p_h, DM, LAT);

    for (int l = 0; l < NL; l++) {
        rmsnorm_kernel<<<ROWS, DM/4>>>(p_h, norm_w + (size_t)l * DM, p_hn);

        // xz = hn @ in_w[l]   (4096x512x2048)
        gemm_mma<128,0,false,false><<<dim3(2*DIN/128, ROWS/128), 256, SMEM_BN128>>>(
            p_hn, DM, in_w + (size_t)l * DM * 2 * DIN, nullptr, nullptr,
            p_xz, 2*DIN, DM);

        conv_silu_kernel<<<(ROWS*DIN)/256, 256>>>(
            p_xz, conv_w + (size_t)l * DIN * 4, conv_b + (size_t)l * DIN, p_xc);

        // dbl = xc @ xproj_w[l]   (4096x1024x64), BN=64
        gemm_mma<64,0,false,false><<<dim3(1, ROWS/128), 256, SMEM_BN64>>>(
            p_xc, DIN, xproj_w + (size_t)l * DIN * 64, nullptr, nullptr,
            p_dbl, 64, DIN);

        // dt = softplus(dbl[:, :32] @ dt_w[l] + dt_b[l])   (4096x32x1024)
        gemm_mma<128,1,true,false><<<dim3(DIN/128, ROWS/128), 256, SMEM_BN128>>>(
            p_dbl, 64, dt_w + (size_t)l * DTRANK * DIN, dt_b + (size_t)l * DIN,
            nullptr, p_dt, DIN, DTRANK);

        scan_kernel<<<(BATCH*DIN/2)*32/256, 256>>>(
            p_xc, p_dt, p_dbl,
            A_log + (size_t)l * DIN * DSTATE, Dp + (size_t)l * DIN,
            p_xz + DIN, p_ym);

        // h = h + ym @ out_w[l]   (4096x1024x512)
        gemm_mma<128,0,false,true><<<dim3(DM/128, ROWS/128), 256, SMEM_BN128>>>(
            p_ym, DIN, out_w + (size_t)l * DIN * DM, nullptr, p_h,
            p_h, DM, DIN);
    }

    // logits = h @ lin2_w + lin2_b   (4096x512x1024)
    gemm_mma<128,0,true,false><<<dim3(LAT/128, ROWS/128), 256, SMEM_BN128>>>(
        p_h, DM, lin2_w, lin2_b, nullptr, p_logits, LAT, DM);

    softmax_kernel<<<(ROWS*32*32)/256, 256>>>(p_logits, outp);
}

// round 4
// speedup vs baseline: 2.7923x; 2.0162x over previous
#include <cuda_runtime.h>
#include <math.h>
#include <stdint.h>

// ---------------- problem constants ----------------
#define BATCH 4
#define SEQ 1024
#define DM 512          // d_model
#define LAT 1024        // latent
#define DIN 1024        // d_inner
#define DSTATE 16
#define DTRANK 32
#define NL 4
#define ROWS (BATCH*SEQ)   // 4096

// ---------------- scratch ----------------
__device__ float g_h[ROWS*DM];
__device__ float g_hn[ROWS*DM];
__device__ float g_xz[ROWS*2*DIN];
__device__ float g_xc[ROWS*DIN];
__device__ float g_dbl[ROWS*64];
__device__ float g_dt[ROWS*DIN];
__device__ float g_ym[ROWS*DIN];
__device__ float g_logits[ROWS*LAT];

// ---------------- helpers ----------------
__device__ __forceinline__ float softplusf(float x) {
    return x > 20.f ? x : log1pf(__expf(x));
}
__device__ __forceinline__ float siluf(float x) {
    return x / (1.f + __expf(-x));
}
__device__ __forceinline__ uint32_t smem_u32(const void* p) {
    uint32_t a;
    asm("{ .reg .u64 t; cvta.to.shared.u64 t, %1; cvt.u32.u64 %0, t; }" : "=r"(a) : "l"(p));
    return a;
}
__device__ __forceinline__ void mma_16n8k8(float* d, const uint32_t* a, const uint32_t* b) {
    asm volatile(
        "mma.sync.aligned.m16n8k8.row.col.f32.tf32.tf32.f32 "
        "{%0,%1,%2,%3}, {%4,%5,%6,%7}, {%8,%9}, {%0,%1,%2,%3};"
        : "+f"(d[0]), "+f"(d[1]), "+f"(d[2]), "+f"(d[3])
        : "r"(a[0]), "r"(a[1]), "r"(a[2]), "r"(a[3]), "r"(b[0]), "r"(b[1]));
}

// ---------------- tf32 mma.sync GEMM, 3-stage cp.async ----------------
// C[M,N] = act(A[M,K](lda) @ B[K,N] + bias) + resid
// BM=128, BK=32, BN in {64,128}. 256 threads = 8 warps (2x4), warp tile 64x(BN/4).
// A raw fp32 bits fed to HMMA (tf32 truncation) -> no cvt, both operands cp.async.
template<int BN, int ACT, bool BIAS, bool RESID>
__global__ __launch_bounds__(256) void gemm_mma(
    const float* __restrict__ A, int lda,
    const float* __restrict__ B,
    const float* __restrict__ bias,
    const float* __restrict__ resid,
    float* __restrict__ C, int N, int K)
{
    constexpr int BM = 128, BK = 32, STAGES = 3;
    constexpr int ASTR = 36;                  // [m][k] row stride (words)
    constexpr int BSTR = BN + 8;              // [k][n] row stride (words), conflict-free
    constexpr int AWORDS = BM * ASTR;         // 4608
    constexpr int BWORDS = BK * BSTR;
    constexpr int STAGE_W = AWORDS + BWORDS;
    constexpr int NI = BN / 32;               // m16n8 tiles per warp in N
    constexpr int BCP = BN / 32;              // B cp.async chunks per thread

    extern __shared__ float smf[];

    const int tid = threadIdx.x;
    const int wid = tid >> 5, lane = tid & 31;
    const int g = lane >> 2, tig = lane & 3;
    const int warpM = wid >> 2, warpN = wid & 3;
    const int bm0 = blockIdx.y * BM, bn0 = blockIdx.x * BN;
    const int KT = K / BK;

    float acc[4][NI][4];
#pragma unroll
    for (int mi = 0; mi < 4; mi++)
#pragma unroll
        for (int ni = 0; ni < NI; ni++)
#pragma unroll
            for (int j = 0; j < 4; j++) acc[mi][ni][j] = 0.f;

    auto cp_tile = [&](int kt, int s) {
        float* As = smf + s * STAGE_W;
        float* Bs = As + AWORDS;
        // A: 128 rows x 32 floats -> 1024 16B chunks, 4 per thread
#pragma unroll
        for (int i = 0; i < 4; i++) {
            int c = tid + i * 256;
            int r = c >> 3, k4 = c & 7;
            uint32_t dst = smem_u32(As + r * ASTR + k4 * 4);
            const float* src = A + (size_t)(bm0 + r) * lda + kt * 32 + k4 * 4;
            asm volatile("cp.async.cg.shared.global [%0], [%1], 16;" :: "r"(dst), "l"(src));
        }
        // B: 32 rows x BN floats
#pragma unroll
        for (int i = 0; i < BCP; i++) {
            int c = tid + i * 256;
            int kr = c / (BN / 4), n4 = c % (BN / 4);
            uint32_t dst = smem_u32(Bs + kr * BSTR + n4 * 4);
            const float* src = B + (size_t)(kt * 32 + kr) * N + bn0 + n4 * 4;
            asm volatile("cp.async.cg.shared.global [%0], [%1], 16;" :: "r"(dst), "l"(src));
        }
        asm volatile("cp.async.commit_group;" ::: "memory");
    };

    auto compute = [&](int s) {
        const float* as = smf + s * STAGE_W;
        const float* bs = as + AWORDS;
#pragma unroll
        for (int k8 = 0; k8 < BK; k8 += 8) {
            uint32_t af[4][4];
            uint32_t bf[NI][2];
#pragma unroll
            for (int mi = 0; mi < 4; mi++) {
                const float* p = as + (warpM * 64 + mi * 16 + g) * ASTR + k8 + tig;
                af[mi][0] = __float_as_uint(p[0]);
                af[mi][1] = __float_as_uint(p[8 * ASTR]);
                af[mi][2] = __float_as_uint(p[4]);
                af[mi][3] = __float_as_uint(p[8 * ASTR + 4]);
            }
#pragma unroll
            for (int ni = 0; ni < NI; ni++) {
                const float* q = bs + (k8 + tig) * BSTR + warpN * (BN / 4) + ni * 8 + g;
                bf[ni][0] = __float_as_uint(q[0]);
                bf[ni][1] = __float_as_uint(q[4 * BSTR]);
            }
#pragma unroll
            for (int mi = 0; mi < 4; mi++)
#pragma unroll
                for (int ni = 0; ni < NI; ni++)
                    mma_16n8k8(acc[mi][ni], af[mi], bf[ni]);
        }
    };

    // prologue: fill up to STAGES-1 stages
    const int pre = (KT < STAGES - 1) ? KT : (STAGES - 1);
    for (int s = 0; s < pre; s++) cp_tile(s, s);

    for (int kt = 0; kt < KT; kt++) {
        if (kt + 1 < KT) asm volatile("cp.async.wait_group 1;" ::: "memory");
        else             asm volatile("cp.async.wait_group 0;" ::: "memory");
        __syncthreads();
        compute(kt % STAGES);
        if (kt + STAGES - 1 < KT) cp_tile(kt + STAGES - 1, (kt + STAGES - 1) % STAGES);
        __syncthreads();
    }

    // epilogue: registers -> gmem, fused bias/act/resid
#pragma unroll
    for (int mi = 0; mi < 4; mi++) {
        const int r0 = bm0 + warpM * 64 + mi * 16 + g;
#pragma unroll
        for (int ni = 0; ni < NI; ni++) {
            const int c = bn0 + warpN * (BN / 4) + ni * 8 + tig * 2;
            float2 v0 = make_float2(acc[mi][ni][0], acc[mi][ni][1]);
            float2 v1 = make_float2(acc[mi][ni][2], acc[mi][ni][3]);
            if (BIAS) {
                const float b0 = bias[c], b1 = bias[c + 1];
                v0.x += b0; v0.y += b1; v1.x += b0; v1.y += b1;
            }
            if (ACT == 1) {
                v0.x = softplusf(v0.x); v0.y = softplusf(v0.y);
                v1.x = softplusf(v1.x); v1.y = softplusf(v1.y);
            }
            if (RESID) {
                const float2 r0v = *(const float2*)(resid + (size_t)r0 * N + c);
                const float2 r1v = *(const float2*)(resid + (size_t)(r0 + 8) * N + c);
                v0.x += r0v.x; v0.y += r0v.y; v1.x += r1v.x; v1.y += r1v.y;
            }
            *(float2*)(C + (size_t)r0 * N + c) = v0;
            *(float2*)(C + (size_t)(r0 + 8) * N + c) = v1;
        }
    }
}

// ---------------- rmsnorm ----------------
__global__ void rmsnorm_kernel(const float* __restrict__ x,
                               const float* __restrict__ w,
                               float* __restrict__ o)
{
    const int row = blockIdx.x;
    const int t = threadIdx.x;
    const float4 v = reinterpret_cast<const float4*>(x + (size_t)row * DM)[t];
    float ss = v.x * v.x + v.y * v.y + v.z * v.z + v.w * v.w;
#pragma unroll
    for (int off = 16; off; off >>= 1) ss += __shfl_xor_sync(~0u, ss, off);
    __shared__ float sm[4];
    if ((t & 31) == 0) sm[t >> 5] = ss;
    __syncthreads();
    const float tot = sm[0] + sm[1] + sm[2] + sm[3];
    const float sc = rsqrtf(tot / (float)DM + 1e-5f);
    const float4 wv = reinterpret_cast<const float4*>(w)[t];
    float4 r;
    r.x = v.x * sc * wv.x; r.y = v.y * sc * wv.y;
    r.z = v.z * sc * wv.z; r.w = v.w * sc * wv.w;
    reinterpret_cast<float4*>(o + (size_t)row * DM)[t] = r;
}

// ---------------- causal depthwise conv (K=4) + silu ----------------
__global__ void conv_silu_kernel(const float* __restrict__ xz,
                                 const float* __restrict__ w,
                                 const float* __restrict__ b,
                                 float* __restrict__ out)
{
    const int idx = blockIdx.x * blockDim.x + threadIdx.x;
    const int d = idx & (DIN - 1);
    const int bt = idx >> 10;
    const int t = bt & (SEQ - 1);
    const float* col = xz + (size_t)bt * (2 * DIN) + d;
    const float w0 = w[d * 4 + 0], w1 = w[d * 4 + 1];
    const float w2 = w[d * 4 + 2], w3 = w[d * 4 + 3];
    float acc = b[d] + w3 * col[0];
    if (t >= 1) acc = fmaf(w2, col[-1 * 2 * DIN], acc);
    if (t >= 2) acc = fmaf(w1, col[-2 * 2 * DIN], acc);
    if (t >= 3) acc = fmaf(w0, col[-3 * 2 * DIN], acc);
    out[idx] = siluf(acc);
}

// ---------------- selective scan, 4-step software pipeline ----------------
__global__ void scan_kernel(const float* __restrict__ u,
                            const float* __restrict__ dt,
                            const float* __restrict__ dbl,
                            const float* __restrict__ A_log,
                            const float* __restrict__ Dp,
                            const float* __restrict__ z,
                            float* __restrict__ ym)
{
    const int warp = (blockIdx.x * blockDim.x + threadIdx.x) >> 5;
    const int lane = threadIdx.x & 31;
    const int n = lane & 15;
    const int ch = warp * 2 + (lane >> 4);
    const int b = ch >> 10;
    const int d = ch & (DIN - 1);

    const float An = -__expf(A_log[d * DSTATE + n]);
    const float Dd = Dp[d];
    float h = 0.f;

    const float* dtp = dt + (size_t)b * SEQ * DIN + d;
    const float* up  = u  + (size_t)b * SEQ * DIN + d;
    const float* blp = dbl + (size_t)b * SEQ * 64 + DTRANK + n;
    const float* zp  = z  + (size_t)b * SEQ * 2 * DIN + d;
    float* yp        = ym + (size_t)b * SEQ * DIN + d;

    float vdt[4], vu[4], vB[4], vC[4], vz[4];
#pragma unroll
    for (int j = 0; j < 4; j++) {
        vdt[j] = dtp[j * DIN];
        vu[j]  = up[j * DIN];
        vB[j]  = blp[j * 64];
        vC[j]  = blp[j * 64 + DSTATE];
        vz[j]  = zp[(size_t)j * 2 * DIN];
    }

    for (int t0 = 0; t0 < SEQ; t0 += 4) {
        float ndt[4], nu[4], nB[4], nC[4], nz[4];
        const bool more = (t0 + 4 < SEQ);
#pragma unroll
        for (int j = 0; j < 4; j++) {
            const int t = t0 + 4 + j;
            if (more) {                 // SEQ % 4 == 0, whole block valid together
                ndt[j] = dtp[(size_t)t * DIN];
                nu[j]  = up[(size_t)t * DIN];
                nB[j]  = blp[(size_t)t * 64];
                nC[j]  = blp[(size_t)t * 64 + DSTATE];
                nz[j]  = zp[(size_t)t * 2 * DIN];
            } else {
                ndt[j] = nu[j] = nB[j] = nC[j] = nz[j] = 0.f;
            }
        }
#pragma unroll
        for (int j = 0; j < 4; j++) {
            const int t = t0 + j;
            const float dA = __expf(vdt[j] * An);
            h = fmaf(dA, h, vdt[j] * vu[j] * vB[j]);
            float p = h * vC[j];
            p += __shfl_xor_sync(~0u, p, 8);
            p += __shfl_xor_sync(~0u, p, 4);
            p += __shfl_xor_sync(~0u, p, 2);
            p += __shfl_xor_sync(~0u, p, 1);
            if (n == 0) {
                const float y = p + vu[j] * Dd;
                yp[(size_t)t * DIN] = y * siluf(vz[j]);
            }
        }
#pragma unroll
        for (int j = 0; j < 4; j++) {
            vdt[j] = ndt[j]; vu[j] = nu[j]; vB[j] = nB[j]; vC[j] = nC[j]; vz[j] = nz[j];
        }
    }
}

// ---------------- grouped softmax ----------------
__global__ void softmax_kernel(const float* __restrict__ logits,
                               float* __restrict__ out)
{
    const int g = (blockIdx.x * blockDim.x + threadIdx.x) >> 5;
    const int lane = threadIdx.x & 31;
    const size_t base = (size_t)(g >> 5) * LAT + (size_t)(g & 31) * 32;
    const float v = logits[base + lane];
    float m = v;
#pragma unroll
    for (int off = 16; off; off >>= 1) m = fmaxf(m, __shfl_xor_sync(~0u, m, off));
    const float e = __expf(v - m);
    float s = e;
#pragma unroll
    for (int off = 16; off; off >>= 1) s += __shfl_xor_sync(~0u, s, off);
    out[base + lane] = e / s;
}

// ---------------- host side ----------------
static inline float* symaddr(const void* sym) {
    void* p = nullptr;
    cudaGetSymbolAddress(&p, sym);
    return (float*)p;
}

// smem bytes: 3 stages * (128*36 + 32*(BN+8)) words * 4
#define SMEM_BN128 (3 * (128*36 + 32*136) * 4)   // 107520
#define SMEM_BN64  (3 * (128*36 + 32*72)  * 4)   // 82944

extern "C" void kernel_launch(void* const* d_in, const int* in_sizes, int n_in,
                              void* d_out, int out_size)
{
    const float* x       = (const float*)d_in[0];
    const float* lin1_w  = (const float*)d_in[1];
    const float* lin1_b  = (const float*)d_in[2];
    const float* norm_w  = (const float*)d_in[3];
    const float* in_w    = (const float*)d_in[4];
    const float* conv_w  = (const float*)d_in[5];
    const float* conv_b  = (const float*)d_in[6];
    const float* xproj_w = (const float*)d_in[7];
    const float* dt_w    = (const float*)d_in[8];
    const float* dt_b    = (const float*)d_in[9];
    const float* A_log   = (const float*)d_in[10];
    const float* Dp      = (const float*)d_in[11];
    const float* out_w   = (const float*)d_in[12];
    const float* lin2_w  = (const float*)d_in[13];
    const float* lin2_b  = (const float*)d_in[14];
    float* outp          = (float*)d_out;

    float* p_h      = symaddr(g_h);
    float* p_hn     = symaddr(g_hn);
    float* p_xz     = symaddr(g_xz);
    float* p_xc     = symaddr(g_xc);
    float* p_dbl    = symaddr(g_dbl);
    float* p_dt     = symaddr(g_dt);
    float* p_ym     = symaddr(g_ym);
    float* p_logits = symaddr(g_logits);

    cudaFuncSetAttribute(gemm_mma<128,0,true,false>,  cudaFuncAttributeMaxDynamicSharedMemorySize, SMEM_BN128);
    cudaFuncSetAttribute(gemm_mma<128,0,false,false>, cudaFuncAttributeMaxDynamicSharedMemorySize, SMEM_BN128);
    cudaFuncSetAttribute(gemm_mma<128,1,true,false>,  cudaFuncAttributeMaxDynamicSharedMemorySize, SMEM_BN128);
    cudaFuncSetAttribute(gemm_mma<128,0,false,true>,  cudaFuncAttributeMaxDynamicSharedMemorySize, SMEM_BN128);
    cudaFuncSetAttribute(gemm_mma<64,0,false,false>,  cudaFuncAttributeMaxDynamicSharedMemorySize, SMEM_BN64);

    // 1) h = x @ lin1_w + lin1_b   (4096x1024x512)
    gemm_mma<128,0,true,false><<<dim3(DM/128, ROWS/128), 256, SMEM_BN128>>>(
        x, LAT, lin1_w, lin1_b, nullptr, p_h, DM, LAT);

    for (int l = 0; l < NL; l++) {
        rmsnorm_kernel<<<ROWS, DM/4>>>(p_h, norm_w + (size_t)l * DM, p_hn);

        // xz = hn @ in_w[l]   (4096x512x2048)
        gemm_mma<128,0,false,false><<<dim3(2*DIN/128, ROWS/128), 256, SMEM_BN128>>>(
            p_hn, DM, in_w + (size_t)l * DM * 2 * DIN, nullptr, nullptr,
            p_xz, 2*DIN, DM);

        conv_silu_kernel<<<(ROWS*DIN)/256, 256>>>(
            p_xz, conv_w + (size_t)l * DIN * 4, conv_b + (size_t)l * DIN, p_xc);

        // dbl = xc @ xproj_w[l]   (4096x1024x64), BN=64
        gemm_mma<64,0,false,false><<<dim3(1, ROWS/128), 256, SMEM_BN64>>>(
            p_xc, DIN, xproj_w + (size_t)l * DIN * 64, nullptr, nullptr,
            p_dbl, 64, DIN);

        // dt = softplus(dbl[:, :32] @ dt_w[l] + dt_b[l])   (4096x32x1024)
        gemm_mma<128,1,true,false><<<dim3(DIN/128, ROWS/128), 256, SMEM_BN128>>>(
            p_dbl, 64, dt_w + (size_t)l * DTRANK * DIN, dt_b + (size_t)l * DIN,
            nullptr, p_dt, DIN, DTRANK);

        scan_kernel<<<(BATCH*DIN/2)*32/256, 256>>>(
            p_xc, p_dt, p_dbl,
            A_log + (size_t)l * DIN * DSTATE, Dp + (size_t)l * DIN,
            p_xz + DIN, p_ym);

        // h = h + ym @ out_w[l]   (4096x1024x512)
        gemm_mma<128,0,false,true><<<dim3(DM/128, ROWS/128), 256, SMEM_BN128>>>(
            p_ym, DIN, out_w + (size_t)l * DIN * DM, nullptr, p_h,
            p_h, DM, DIN);
    }

    // logits = h @ lin2_w + lin2_b   (4096x512x1024)
    gemm_mma<128,0,true,false><<<dim3(LAT/128, ROWS/128), 256, SMEM_BN128>>>(
        p_h, DM, lin2_w, lin2_b, nullptr, p_logits, LAT, DM);

    softmax_kernel<<<(ROWS*32*32)/256, 256>>>(p_logits, outp);
}